// round 14
// baseline (speedup 1.0000x reference)
#include <cuda_runtime.h>
#include <cuda_fp16.h>
#include <math.h>

#define NNODES 100000
#define NEDGES 1600000
#define INC 128
#define HID 128
#define OUTC 18
#define NB 98

// ---------------- scratch ----------------
__device__ __align__(16) float g_dinv[NNODES];
__device__ __align__(16) __half g_xh[(size_t)NNODES * INC];
__device__ __align__(16) __half g_w1h[INC * HID];
__device__ __align__(16) float g_h1f[(size_t)NNODES * HID];    // x @ W1, fp32
__device__ __align__(16) __half g_h2h[(size_t)NNODES * OUTC];
__device__ int g_degi[NNODES];
__device__ int g_rowstart[NNODES + 1];
__device__ int g_cursor[NNODES];
__device__ __align__(8) int2 g_cadj[NEDGES];   // {src, dinv[src] bits}
__device__ int g_bsum[128];
__device__ int g_is64;
__device__ unsigned int g_arr1;
__device__ unsigned int g_arr2;

// packed f32x2 helpers
#define FMA2(acc, w, v) \
    asm("fma.rn.f32x2 %0, %1, %2, %0;" : "+l"(acc) : "l"(w), "l"(v))
#define PACK2(d, f) \
    asm("mov.b64 %0, {%1, %1};" : "=l"(d) : "r"(__float_as_uint(f)))
#define PACKAB(d, a, b) \
    asm("mov.b64 %0, {%1, %2};" : "=l"(d) : "r"(__float_as_uint(a)), "r"(__float_as_uint(b)))
#define UNPACK2(lo, hi, d) \
    asm("mov.b64 {%0, %1}, %2;" : "=r"(lo), "=r"(hi) : "l"(d))

// ---------------- K1: detect + degree count + fp16 convert ----------------
__global__ void k_prep(const void* __restrict__ ei,
                       const float* __restrict__ x, const float* __restrict__ W1) {
    __shared__ int s_is64;
    const unsigned int* eiw = (const unsigned int*)ei;
    if (threadIdx.x < 32) {
        unsigned int any = 0;
        for (int q = threadIdx.x; q < 128; q += 32) any |= eiw[2 * q + 1];
        unsigned int b = __ballot_sync(0xffffffffu, any != 0u);
        if (threadIdx.x == 0) s_is64 = (b == 0u);
    }
    __syncthreads();
    int i = blockIdx.x * blockDim.x + threadIdx.x;
    if (i == 0) g_is64 = s_is64;
    if (i < NEDGES) {
        int d = s_is64 ? (int)((const long long*)ei)[NEDGES + i]
                       : ((const int*)ei)[NEDGES + i];
        atomicAdd(&g_degi[d], 1);
    }
    if (i < NNODES * INC / 4) {
        float4 v = ((const float4*)x)[i];
        __half2 lo = __floats2half2_rn(v.x, v.y);
        __half2 hi = __floats2half2_rn(v.z, v.w);
        uint2 u;
        u.x = *(unsigned int*)&lo;
        u.y = *(unsigned int*)&hi;
        *(uint2*)(g_xh + (size_t)i * 4) = u;
    }
    if (i < INC * HID / 4) {
        float4 v = ((const float4*)W1)[i];
        __half2 lo = __floats2half2_rn(v.x, v.y);
        __half2 hi = __floats2half2_rn(v.z, v.w);
        uint2 u;
        u.x = *(unsigned int*)&lo;
        u.y = *(unsigned int*)&hi;
        *(uint2*)(g_w1h + (size_t)i * 4) = u;
    }
}

// ---------------- GEMM1 tensor cores, 512 thr, cp.async (fp32 output) ----------------
#define XS_STRIDE 144
#define WS_STRIDE 272
#define SX_BYTES (128 * XS_STRIDE)
#define SW_BYTES (64 * WS_STRIDE)
#define PHASE_BYTES (SX_BYTES + SW_BYTES)
#define GEMM1_SMEM (2 * PHASE_BYTES)

__device__ __forceinline__ void cp16(unsigned int dst, const void* src, int srcsize) {
    asm volatile("cp.async.cg.shared.global [%0], [%1], 16, %2;"
                 :: "r"(dst), "l"(src), "r"(srcsize));
}

__global__ __launch_bounds__(512, 2) void k_gemm1_mma() {
    extern __shared__ __align__(16) unsigned char dynsmem[];
    const int tid = threadIdx.x;
    const int wid = tid >> 5;
    const int lane = tid & 31;
    const int slab = wid >> 1;
    const int half = wid & 1;
    const int row0 = blockIdx.x * 128;

#pragma unroll
    for (int kp = 0; kp < 2; kp++) {
        unsigned char* s_x = dynsmem + kp * PHASE_BYTES;
        unsigned char* s_w = s_x + SX_BYTES;
        for (int i = tid; i < 128 * 8; i += 512) {
            int r = i >> 3, c = i & 7;
            const void* src = g_xh + (size_t)(row0 + r) * INC + kp * 64 + c * 8;
            int vsz = (row0 + r < NNODES) ? 16 : 0;
            unsigned int dst = (unsigned int)__cvta_generic_to_shared(s_x + r * XS_STRIDE + c * 16);
            cp16(dst, src, vsz);
        }
        for (int i = tid; i < 64 * 16; i += 512) {
            int r = i >> 4, c = i & 15;
            const void* src = g_w1h + (size_t)(kp * 64 + r) * HID + c * 8;
            unsigned int dst = (unsigned int)__cvta_generic_to_shared(s_w + r * WS_STRIDE + c * 16);
            cp16(dst, src, 16);
        }
        asm volatile("cp.async.commit_group;");
    }

    float acc[8][4];
#pragma unroll
    for (int t = 0; t < 8; t++)
#pragma unroll
        for (int q = 0; q < 4; q++) acc[t][q] = 0.0f;

#pragma unroll
    for (int kp = 0; kp < 2; kp++) {
        if (kp == 0) asm volatile("cp.async.wait_group 1;");
        else         asm volatile("cp.async.wait_group 0;");
        __syncthreads();
        unsigned char* s_x = dynsmem + kp * PHASE_BYTES;
        unsigned char* s_w = s_x + SX_BYTES;

#pragma unroll
        for (int kk = 0; kk < 4; kk++) {
            unsigned int a0, a1, a2, a3;
            {
                const unsigned char* p = s_x + (slab * 16 + (lane & 15)) * XS_STRIDE
                                             + kk * 32 + (lane >> 4) * 16;
                unsigned int sa = (unsigned int)__cvta_generic_to_shared(p);
                asm volatile("ldmatrix.sync.aligned.m8n8.x4.shared.b16 {%0,%1,%2,%3}, [%4];"
                             : "=r"(a0), "=r"(a1), "=r"(a2), "=r"(a3) : "r"(sa));
            }
#pragma unroll
            for (int j = 0; j < 4; j++) {
                unsigned int b0, b1, b2, b3;
                const unsigned char* p = s_w + (kk * 16 + (lane & 15)) * WS_STRIDE
                                             + half * 128 + j * 32 + (lane >> 4) * 16;
                unsigned int sb = (unsigned int)__cvta_generic_to_shared(p);
                asm volatile("ldmatrix.sync.aligned.m8n8.x4.trans.shared.b16 {%0,%1,%2,%3}, [%4];"
                             : "=r"(b0), "=r"(b1), "=r"(b2), "=r"(b3) : "r"(sb));
                asm volatile("mma.sync.aligned.m16n8k16.row.col.f32.f16.f16.f32 "
                             "{%0,%1,%2,%3}, {%4,%5,%6,%7}, {%8,%9}, {%0,%1,%2,%3};"
                             : "+f"(acc[2 * j][0]), "+f"(acc[2 * j][1]),
                               "+f"(acc[2 * j][2]), "+f"(acc[2 * j][3])
                             : "r"(a0), "r"(a1), "r"(a2), "r"(a3), "r"(b0), "r"(b1));
                asm volatile("mma.sync.aligned.m16n8k16.row.col.f32.f16.f16.f32 "
                             "{%0,%1,%2,%3}, {%4,%5,%6,%7}, {%8,%9}, {%0,%1,%2,%3};"
                             : "+f"(acc[2 * j + 1][0]), "+f"(acc[2 * j + 1][1]),
                               "+f"(acc[2 * j + 1][2]), "+f"(acc[2 * j + 1][3])
                             : "r"(a0), "r"(a1), "r"(a2), "r"(a3), "r"(b2), "r"(b3));
            }
        }
        __syncthreads();
    }

    int gr = lane >> 2;
    int gc = (lane & 3) * 2;
    int r1 = row0 + slab * 16 + gr;
    int r2 = r1 + 8;
#pragma unroll
    for (int t = 0; t < 8; t++) {
        int col = half * 64 + t * 8 + gc;
        if (r1 < NNODES)
            *(float2*)(g_h1f + (size_t)r1 * HID + col) = make_float2(acc[t][0], acc[t][1]);
        if (r2 < NNODES)
            *(float2*)(g_h1f + (size_t)r2 * HID + col) = make_float2(acc[t][2], acc[t][3]);
    }
}

// ---------------- scan + dinv + CSR fill (persistent; unchanged) ----------------
__device__ __forceinline__ void grid_barrier(unsigned int* cnt) {
    __syncthreads();
    __threadfence();
    if (threadIdx.x == 0) {
        unsigned int old = atomicAdd(cnt, 1u);
        unsigned int target = (old / NB + 1u) * NB;
        while (atomicAdd(cnt, 0u) < target) {}
    }
    __syncthreads();
}

__global__ __launch_bounds__(1024) void k_scanfill(const void* __restrict__ ei) {
    __shared__ int sh[1024];
    __shared__ int sp[128];
    const int b = blockIdx.x;
    const int t = threadIdx.x;
    const int i = b * 1024 + t;

    int deg = (i < NNODES) ? g_degi[i] : 0;
    sh[t] = deg;
    __syncthreads();
    for (int off = 1; off < 1024; off <<= 1) {
        int v = (t >= off) ? sh[t - off] : 0;
        __syncthreads();
        sh[t] += v;
        __syncthreads();
    }
    int incl = sh[t];
    if (t == 1023) g_bsum[b] = incl;

    grid_barrier(&g_arr1);

    if (t < 128) sp[t] = (t < NB) ? g_bsum[t] : 0;
    __syncthreads();
    for (int off = 1; off < 128; off <<= 1) {
        int v = (t < 128 && t >= off) ? sp[t - off] : 0;
        __syncthreads();
        if (t < 128) sp[t] += v;
        __syncthreads();
    }
    int ebase = (b == 0) ? 0 : sp[b - 1];
    if (i < NNODES) {
        int r = ebase + incl - deg;
        g_rowstart[i] = r;
        g_cursor[i] = r;
        g_dinv[i] = rsqrtf(1.0f + (float)deg);
        g_degi[i] = 0;
    }
    if (i == 0) g_rowstart[NNODES] = NEDGES;

    grid_barrier(&g_arr2);

    const int is64 = g_is64;
    const long long* p64 = (const long long*)ei;
    const int* p32 = (const int*)ei;
    for (int e = b * 1024 + t; e < NEDGES; e += NB * 1024) {
        int s, d;
        if (is64) { s = (int)p64[e]; d = (int)p64[NEDGES + e]; }
        else      { s = p32[e];      d = p32[NEDGES + e]; }
        int pos = atomicAdd(&g_cursor[d], 1);
        g_cadj[pos] = make_int2(s, __float_as_int(g_dinv[s]));
    }
}

// ---------------- Layer 1: fp32 gather + FFMA2 + MMA GEMM2 epilogue ----------------
#define AGH_STRIDE 272   // bytes per s_aggh row: 128 halfs + 8 pad
#define W2H_STRIDE 80    // bytes per s_w2h row: 32 halfs + 8 pad
__global__ __launch_bounds__(256, 5) void k_layer1(const float* __restrict__ b1,
                                                   const float* __restrict__ W2) {
    __shared__ __align__(16) unsigned char s_aggh[16 * AGH_STRIDE];
    __shared__ __align__(16) unsigned char s_w2h[128 * W2H_STRIDE];

    for (int i = threadIdx.x; i < 128 * 40 / 2; i += blockDim.x)
        ((unsigned int*)s_w2h)[i] = 0u;
    __syncthreads();
    for (int i = threadIdx.x; i < HID * OUTC; i += blockDim.x) {
        int k = i / OUTC, oc = i - k * OUTC;
        *(__half*)(s_w2h + k * W2H_STRIDE + oc * 2) = __float2half_rn(W2[i]);
    }

    const int wid = threadIdx.x >> 5;
    const int lane = threadIdx.x & 31;
    const int h = lane >> 4;
    const int hl = lane & 15;
    const int node = blockIdx.x * 16 + wid * 2 + h;   // exact grid

    {
        float din = g_dinv[node];
        int rs = g_rowstart[node];
        int re = g_rowstart[node + 1];

        // self-loop + bias (fp32)
        const float* myrow = g_h1f + (size_t)node * HID + hl * 8;
        float4 sa = *(const float4*)(myrow);
        float4 sb = *(const float4*)(myrow + 4);
        float di2 = din * din;
        float4 ba = *(const float4*)(b1 + hl * 8);
        float4 bb = *(const float4*)(b1 + hl * 8 + 4);
        unsigned long long acc0, acc1, acc2, acc3;
        PACKAB(acc0, ba.x + di2 * sa.x, ba.y + di2 * sa.y);
        PACKAB(acc1, ba.z + di2 * sa.z, ba.w + di2 * sa.w);
        PACKAB(acc2, bb.x + di2 * sb.x, bb.y + di2 * sb.y);
        PACKAB(acc3, bb.z + di2 * sb.z, bb.w + di2 * sb.w);

        int j = rs;
        for (; j + 2 <= re; j += 2) {
            int2 e0 = g_cadj[j];
            int2 e1 = g_cadj[j + 1];
            unsigned long long w0p, w1p;
            PACK2(w0p, __int_as_float(e0.y) * din);
            PACK2(w1p, __int_as_float(e1.y) * din);
            const double2* r0 = (const double2*)(g_h1f + (size_t)e0.x * HID + hl * 8);
            const double2* r1 = (const double2*)(g_h1f + (size_t)e1.x * HID + hl * 8);
            double2 v0a = r0[0], v0b = r0[1];
            double2 v1a = r1[0], v1b = r1[1];
            FMA2(acc0, w0p, __double_as_longlong(v0a.x));
            FMA2(acc1, w0p, __double_as_longlong(v0a.y));
            FMA2(acc2, w0p, __double_as_longlong(v0b.x));
            FMA2(acc3, w0p, __double_as_longlong(v0b.y));
            FMA2(acc0, w1p, __double_as_longlong(v1a.x));
            FMA2(acc1, w1p, __double_as_longlong(v1a.y));
            FMA2(acc2, w1p, __double_as_longlong(v1b.x));
            FMA2(acc3, w1p, __double_as_longlong(v1b.y));
        }
        if (j < re) {
            int2 e0 = g_cadj[j];
            unsigned long long w0p;
            PACK2(w0p, __int_as_float(e0.y) * din);
            const double2* r0 = (const double2*)(g_h1f + (size_t)e0.x * HID + hl * 8);
            double2 v0a = r0[0], v0b = r0[1];
            FMA2(acc0, w0p, __double_as_longlong(v0a.x));
            FMA2(acc1, w0p, __double_as_longlong(v0a.y));
            FMA2(acc2, w0p, __double_as_longlong(v0b.x));
            FMA2(acc3, w0p, __double_as_longlong(v0b.y));
        }

        // unpack, ReLU, fp16 pack -> smem staging
        unsigned int l0, h0, l1, h1, l2, h2, l3, h3;
        UNPACK2(l0, h0, acc0);
        UNPACK2(l1, h1, acc1);
        UNPACK2(l2, h2, acc2);
        UNPACK2(l3, h3, acc3);
        __half2 p0 = __floats2half2_rn(fmaxf(__uint_as_float(l0), 0.f), fmaxf(__uint_as_float(h0), 0.f));
        __half2 p1 = __floats2half2_rn(fmaxf(__uint_as_float(l1), 0.f), fmaxf(__uint_as_float(h1), 0.f));
        __half2 p2 = __floats2half2_rn(fmaxf(__uint_as_float(l2), 0.f), fmaxf(__uint_as_float(h2), 0.f));
        __half2 p3 = __floats2half2_rn(fmaxf(__uint_as_float(l3), 0.f), fmaxf(__uint_as_float(h3), 0.f));
        uint4 pk;
        pk.x = *(unsigned int*)&p0; pk.y = *(unsigned int*)&p1;
        pk.z = *(unsigned int*)&p2; pk.w = *(unsigned int*)&p3;
        *(uint4*)(s_aggh + (wid * 2 + h) * AGH_STRIDE + hl * 16) = pk;
    }
    __syncthreads();

    // MMA epilogue (warp 0): D[16x18] = s_aggh[16x128] @ s_w2h[128x18]
    if (wid == 0) {
        float acc[3][4];
#pragma unroll
        for (int nt = 0; nt < 3; nt++)
#pragma unroll
            for (int q = 0; q < 4; q++) acc[nt][q] = 0.0f;

#pragma unroll
        for (int kk = 0; kk < 8; kk++) {
            unsigned int a0, a1, a2, a3;
            {
                const unsigned char* p = s_aggh + (lane & 15) * AGH_STRIDE
                                               + kk * 32 + (lane >> 4) * 16;
                unsigned int sa = (unsigned int)__cvta_generic_to_shared(p);
                asm volatile("ldmatrix.sync.aligned.m8n8.x4.shared.b16 {%0,%1,%2,%3}, [%4];"
                             : "=r"(a0), "=r"(a1), "=r"(a2), "=r"(a3) : "r"(sa));
            }
            unsigned int b0, b1, b2, b3, c0, c1, c2, c3;
            {
                const unsigned char* p = s_w2h + (kk * 16 + (lane & 15)) * W2H_STRIDE
                                               + (lane >> 4) * 16;
                unsigned int sb = (unsigned int)__cvta_generic_to_shared(p);
                asm volatile("ldmatrix.sync.aligned.m8n8.x4.trans.shared.b16 {%0,%1,%2,%3}, [%4];"
                             : "=r"(b0), "=r"(b1), "=r"(b2), "=r"(b3) : "r"(sb));
                asm volatile("ldmatrix.sync.aligned.m8n8.x4.trans.shared.b16 {%0,%1,%2,%3}, [%4];"
                             : "=r"(c0), "=r"(c1), "=r"(c2), "=r"(c3) : "r"(sb + 32));
            }
            asm volatile("mma.sync.aligned.m16n8k16.row.col.f32.f16.f16.f32 "
                         "{%0,%1,%2,%3}, {%4,%5,%6,%7}, {%8,%9}, {%0,%1,%2,%3};"
                         : "+f"(acc[0][0]), "+f"(acc[0][1]), "+f"(acc[0][2]), "+f"(acc[0][3])
                         : "r"(a0), "r"(a1), "r"(a2), "r"(a3), "r"(b0), "r"(b1));
            asm volatile("mma.sync.aligned.m16n8k16.row.col.f32.f16.f16.f32 "
                         "{%0,%1,%2,%3}, {%4,%5,%6,%7}, {%8,%9}, {%0,%1,%2,%3};"
                         : "+f"(acc[1][0]), "+f"(acc[1][1]), "+f"(acc[1][2]), "+f"(acc[1][3])
                         : "r"(a0), "r"(a1), "r"(a2), "r"(a3), "r"(b2), "r"(b3));
            asm volatile("mma.sync.aligned.m16n8k16.row.col.f32.f16.f16.f32 "
                         "{%0,%1,%2,%3}, {%4,%5,%6,%7}, {%8,%9}, {%0,%1,%2,%3};"
                         : "+f"(acc[2][0]), "+f"(acc[2][1]), "+f"(acc[2][2]), "+f"(acc[2][3])
                         : "r"(a0), "r"(a1), "r"(a2), "r"(a3), "r"(c0), "r"(c1));
        }

        int gr = lane >> 2;
        int gc = (lane & 3) * 2;
        int n0 = blockIdx.x * 16 + gr;
        int n1 = n0 + 8;
#pragma unroll
        for (int nt = 0; nt < 2; nt++) {
            int c = nt * 8 + gc;
            __half2 hA = __floats2half2_rn(acc[nt][0], acc[nt][1]);
            __half2 hB = __floats2half2_rn(acc[nt][2], acc[nt][3]);
            *(__half2*)(g_h2h + (size_t)n0 * OUTC + c) = hA;
            *(__half2*)(g_h2h + (size_t)n1 * OUTC + c) = hB;
        }
        if (gc == 0) {
            __half2 hA = __floats2half2_rn(acc[2][0], acc[2][1]);
            __half2 hB = __floats2half2_rn(acc[2][2], acc[2][3]);
            *(__half2*)(g_h2h + (size_t)n0 * OUTC + 16) = hA;
            *(__half2*)(g_h2h + (size_t)n1 * OUTC + 16) = hB;
        }
    }
}

// ---------------- Layer 2: 2 nodes/warp, half2 gathers, log_softmax ----------------
__global__ __launch_bounds__(256) void k_layer2(const float* __restrict__ b2,
                                                float* __restrict__ out) {
    const int wid = threadIdx.x >> 5;
    const int lane = threadIdx.x & 31;
    const int h = lane >> 4;
    const int hl = lane & 15;
    const unsigned hmask = h ? 0xffff0000u : 0x0000ffffu;
    const int node = blockIdx.x * 16 + wid * 2 + h;
    if (node >= NNODES) return;

    float din = g_dinv[node];
    int rs = g_rowstart[node];
    int re = g_rowstart[node + 1];

    float2 acc = make_float2(0.f, 0.f);
    if (hl < 9) {
        __half2 hv = *(const __half2*)(g_h2h + (size_t)node * OUTC + 2 * hl);
        float2 f = __half22float2(hv);
        float di2 = din * din;
        acc.x = b2[2 * hl]     + di2 * f.x;
        acc.y = b2[2 * hl + 1] + di2 * f.y;
    }

    for (int base = rs; base < re; base += 16) {
        int j = base + hl;
        int2 ew = (j < re) ? g_cadj[j] : make_int2(0, 0);
        int cnt = min(16, re - base);
        int t = 0;
        for (; t + 4 <= cnt; t += 4) {
            float2 v[4]; float w[4];
#pragma unroll
            for (int q = 0; q < 4; q++) {
                int ss = __shfl_sync(hmask, ew.x, (h << 4) + t + q);
                int wb = __shfl_sync(hmask, ew.y, (h << 4) + t + q);
                w[q] = __int_as_float(wb) * din;
                v[q] = make_float2(0.f, 0.f);
                if (hl < 9)
                    v[q] = __half22float2(*(const __half2*)(g_h2h + (size_t)ss * OUTC + 2 * hl));
            }
#pragma unroll
            for (int q = 0; q < 4; q++) {
                acc.x = fmaf(w[q], v[q].x, acc.x);
                acc.y = fmaf(w[q], v[q].y, acc.y);
            }
        }
        for (; t < cnt; t++) {
            int ss = __shfl_sync(hmask, ew.x, (h << 4) + t);
            int wb = __shfl_sync(hmask, ew.y, (h << 4) + t);
            float w = __int_as_float(wb) * din;
            if (hl < 9) {
                float2 v = __half22float2(*(const __half2*)(g_h2h + (size_t)ss * OUTC + 2 * hl));
                acc.x = fmaf(w, v.x, acc.x);
                acc.y = fmaf(w, v.y, acc.y);
            }
        }
    }

    float m = (hl < 9) ? fmaxf(acc.x, acc.y) : -1e30f;
#pragma unroll
    for (int off = 8; off; off >>= 1)
        m = fmaxf(m, __shfl_xor_sync(hmask, m, off));
    float e = (hl < 9) ? (expf(acc.x - m) + expf(acc.y - m)) : 0.f;
#pragma unroll
    for (int off = 8; off; off >>= 1)
        e += __shfl_xor_sync(hmask, e, off);
    float ls = m + logf(e);
    if (hl < 9) {
        float2 o = make_float2(acc.x - ls, acc.y - ls);
        *(float2*)(out + (size_t)node * OUTC + 2 * hl) = o;
    }
}

// ---------------- launch ----------------
extern "C" void kernel_launch(void* const* d_in, const int* in_sizes, int n_in,
                              void* d_out, int out_size) {
    const float* x = 0; const void* ei = 0;
    const float* W1 = 0; const float* b1 = 0;
    const float* W2 = 0; const float* b2 = 0;
    for (int i = 0; i < n_in; i++) {
        long long sz = in_sizes[i];
        if (sz == (long long)NNODES * INC) x = (const float*)d_in[i];
        else if (sz == 2LL * NEDGES)       ei = d_in[i];
        else if (sz == (long long)INC * HID) W1 = (const float*)d_in[i];
        else if (sz == HID)                b1 = (const float*)d_in[i];
        else if (sz == (long long)HID * OUTC) W2 = (const float*)d_in[i];
        else if (sz == OUTC)               b2 = (const float*)d_in[i];
    }
    float* out = (float*)d_out;

    cudaFuncSetAttribute(k_gemm1_mma, cudaFuncAttributeMaxDynamicSharedMemorySize, GEMM1_SMEM);

    k_prep<<<(NNODES * INC / 4 + 255) / 256, 256>>>(ei, x, W1);                      // 1
    k_gemm1_mma<<<(NNODES + 127) / 128, 512, GEMM1_SMEM>>>();                        // 2
    k_scanfill<<<NB, 1024>>>(ei);                                                    // 3
    k_layer1<<<NNODES / 16, 256>>>(b1, W2);                                          // 4 (profiled)
    {
        long long thr = (long long)NNODES * 16;
        k_layer2<<<(unsigned)((thr + 255) / 256), 256>>>(b2, out);                   // 5
    }
}

// round 15
// speedup vs baseline: 1.2442x; 1.2442x over previous
#include <cuda_runtime.h>
#include <cuda_fp16.h>
#include <math.h>

#define NNODES 100000
#define NEDGES 1600000
#define INC 128
#define HID 128
#define OUTC 18
#define NB 98

// ---------------- scratch ----------------
__device__ __align__(16) float g_dinv[NNODES];
__device__ __align__(16) __half g_xh[(size_t)NNODES * INC];
__device__ __align__(16) __half g_w1h[INC * HID];
__device__ __align__(16) __half g_h1h[(size_t)NNODES * HID];
__device__ __align__(16) __half g_h2h[(size_t)NNODES * OUTC];
__device__ int g_degi[NNODES];
__device__ int g_rowstart[NNODES + 1];
__device__ int g_cursor[NNODES];
__device__ __align__(8) int2 g_cadj[NEDGES];   // {src, dinv[src] bits}
__device__ int g_bsum[128];
__device__ int g_is64;
__device__ unsigned int g_arr1;
__device__ unsigned int g_arr2;

// ---------------- K1: detect + degree count + fp16 convert ----------------
__global__ void k_prep(const void* __restrict__ ei,
                       const float* __restrict__ x, const float* __restrict__ W1) {
    __shared__ int s_is64;
    const unsigned int* eiw = (const unsigned int*)ei;
    if (threadIdx.x < 32) {
        unsigned int any = 0;
        for (int q = threadIdx.x; q < 128; q += 32) any |= eiw[2 * q + 1];
        unsigned int b = __ballot_sync(0xffffffffu, any != 0u);
        if (threadIdx.x == 0) s_is64 = (b == 0u);
    }
    __syncthreads();
    int i = blockIdx.x * blockDim.x + threadIdx.x;
    if (i == 0) g_is64 = s_is64;
    if (i < NEDGES) {
        int d = s_is64 ? (int)((const long long*)ei)[NEDGES + i]
                       : ((const int*)ei)[NEDGES + i];
        atomicAdd(&g_degi[d], 1);
    }
    if (i < NNODES * INC / 4) {
        float4 v = ((const float4*)x)[i];
        __half2 lo = __floats2half2_rn(v.x, v.y);
        __half2 hi = __floats2half2_rn(v.z, v.w);
        uint2 u;
        u.x = *(unsigned int*)&lo;
        u.y = *(unsigned int*)&hi;
        *(uint2*)(g_xh + (size_t)i * 4) = u;
    }
    if (i < INC * HID / 4) {
        float4 v = ((const float4*)W1)[i];
        __half2 lo = __floats2half2_rn(v.x, v.y);
        __half2 hi = __floats2half2_rn(v.z, v.w);
        uint2 u;
        u.x = *(unsigned int*)&lo;
        u.y = *(unsigned int*)&hi;
        *(uint2*)(g_w1h + (size_t)i * 4) = u;
    }
}

// ---------------- GEMM1 tensor cores, 512 thr, cp.async double buffer ----------------
#define XS_STRIDE 144
#define WS_STRIDE 272
#define SX_BYTES (128 * XS_STRIDE)
#define SW_BYTES (64 * WS_STRIDE)
#define PHASE_BYTES (SX_BYTES + SW_BYTES)
#define GEMM1_SMEM (2 * PHASE_BYTES)

__device__ __forceinline__ void cp16(unsigned int dst, const void* src, int srcsize) {
    asm volatile("cp.async.cg.shared.global [%0], [%1], 16, %2;"
                 :: "r"(dst), "l"(src), "r"(srcsize));
}

__global__ __launch_bounds__(512, 2) void k_gemm1_mma() {
    extern __shared__ __align__(16) unsigned char dynsmem[];
    const int tid = threadIdx.x;
    const int wid = tid >> 5;
    const int lane = tid & 31;
    const int slab = wid >> 1;
    const int half = wid & 1;
    const int row0 = blockIdx.x * 128;

#pragma unroll
    for (int kp = 0; kp < 2; kp++) {
        unsigned char* s_x = dynsmem + kp * PHASE_BYTES;
        unsigned char* s_w = s_x + SX_BYTES;
        for (int i = tid; i < 128 * 8; i += 512) {
            int r = i >> 3, c = i & 7;
            const void* src = g_xh + (size_t)(row0 + r) * INC + kp * 64 + c * 8;
            int vsz = (row0 + r < NNODES) ? 16 : 0;
            unsigned int dst = (unsigned int)__cvta_generic_to_shared(s_x + r * XS_STRIDE + c * 16);
            cp16(dst, src, vsz);
        }
        for (int i = tid; i < 64 * 16; i += 512) {
            int r = i >> 4, c = i & 15;
            const void* src = g_w1h + (size_t)(kp * 64 + r) * HID + c * 8;
            unsigned int dst = (unsigned int)__cvta_generic_to_shared(s_w + r * WS_STRIDE + c * 16);
            cp16(dst, src, 16);
        }
        asm volatile("cp.async.commit_group;");
    }

    float acc[8][4];
#pragma unroll
    for (int t = 0; t < 8; t++)
#pragma unroll
        for (int q = 0; q < 4; q++) acc[t][q] = 0.0f;

#pragma unroll
    for (int kp = 0; kp < 2; kp++) {
        if (kp == 0) asm volatile("cp.async.wait_group 1;");
        else         asm volatile("cp.async.wait_group 0;");
        __syncthreads();
        unsigned char* s_x = dynsmem + kp * PHASE_BYTES;
        unsigned char* s_w = s_x + SX_BYTES;

#pragma unroll
        for (int kk = 0; kk < 4; kk++) {
            unsigned int a0, a1, a2, a3;
            {
                const unsigned char* p = s_x + (slab * 16 + (lane & 15)) * XS_STRIDE
                                             + kk * 32 + (lane >> 4) * 16;
                unsigned int sa = (unsigned int)__cvta_generic_to_shared(p);
                asm volatile("ldmatrix.sync.aligned.m8n8.x4.shared.b16 {%0,%1,%2,%3}, [%4];"
                             : "=r"(a0), "=r"(a1), "=r"(a2), "=r"(a3) : "r"(sa));
            }
#pragma unroll
            for (int j = 0; j < 4; j++) {
                unsigned int b0, b1, b2, b3;
                const unsigned char* p = s_w + (kk * 16 + (lane & 15)) * WS_STRIDE
                                             + half * 128 + j * 32 + (lane >> 4) * 16;
                unsigned int sb = (unsigned int)__cvta_generic_to_shared(p);
                asm volatile("ldmatrix.sync.aligned.m8n8.x4.trans.shared.b16 {%0,%1,%2,%3}, [%4];"
                             : "=r"(b0), "=r"(b1), "=r"(b2), "=r"(b3) : "r"(sb));
                asm volatile("mma.sync.aligned.m16n8k16.row.col.f32.f16.f16.f32 "
                             "{%0,%1,%2,%3}, {%4,%5,%6,%7}, {%8,%9}, {%0,%1,%2,%3};"
                             : "+f"(acc[2 * j][0]), "+f"(acc[2 * j][1]),
                               "+f"(acc[2 * j][2]), "+f"(acc[2 * j][3])
                             : "r"(a0), "r"(a1), "r"(a2), "r"(a3), "r"(b0), "r"(b1));
                asm volatile("mma.sync.aligned.m16n8k16.row.col.f32.f16.f16.f32 "
                             "{%0,%1,%2,%3}, {%4,%5,%6,%7}, {%8,%9}, {%0,%1,%2,%3};"
                             : "+f"(acc[2 * j + 1][0]), "+f"(acc[2 * j + 1][1]),
                               "+f"(acc[2 * j + 1][2]), "+f"(acc[2 * j + 1][3])
                             : "r"(a0), "r"(a1), "r"(a2), "r"(a3), "r"(b2), "r"(b3));
            }
        }
        __syncthreads();
    }

    int gr = lane >> 2;
    int gc = (lane & 3) * 2;
    int r1 = row0 + slab * 16 + gr;
    int r2 = r1 + 8;
#pragma unroll
    for (int t = 0; t < 8; t++) {
        int col = half * 64 + t * 8 + gc;
        if (r1 < NNODES) {
            __half2 h = __floats2half2_rn(acc[t][0], acc[t][1]);
            *(__half2*)(g_h1h + (size_t)r1 * HID + col) = h;
        }
        if (r2 < NNODES) {
            __half2 h = __floats2half2_rn(acc[t][2], acc[t][3]);
            *(__half2*)(g_h1h + (size_t)r2 * HID + col) = h;
        }
    }
}

// ---------------- scan + dinv + CSR fill (persistent, grid barrier) ----------------
__device__ __forceinline__ void grid_barrier(unsigned int* cnt) {
    __syncthreads();
    __threadfence();
    if (threadIdx.x == 0) {
        unsigned int old = atomicAdd(cnt, 1u);
        unsigned int target = (old / NB + 1u) * NB;
        while (atomicAdd(cnt, 0u) < target) {}
    }
    __syncthreads();
}

__global__ __launch_bounds__(1024) void k_scanfill(const void* __restrict__ ei) {
    __shared__ int sh[1024];
    __shared__ int sp[128];
    const int b = blockIdx.x;
    const int t = threadIdx.x;
    const int i = b * 1024 + t;

    int deg = (i < NNODES) ? g_degi[i] : 0;
    sh[t] = deg;
    __syncthreads();
    for (int off = 1; off < 1024; off <<= 1) {
        int v = (t >= off) ? sh[t - off] : 0;
        __syncthreads();
        sh[t] += v;
        __syncthreads();
    }
    int incl = sh[t];
    if (t == 1023) g_bsum[b] = incl;

    grid_barrier(&g_arr1);

    if (t < 128) sp[t] = (t < NB) ? g_bsum[t] : 0;
    __syncthreads();
    for (int off = 1; off < 128; off <<= 1) {
        int v = (t < 128 && t >= off) ? sp[t - off] : 0;
        __syncthreads();
        if (t < 128) sp[t] += v;
        __syncthreads();
    }
    int ebase = (b == 0) ? 0 : sp[b - 1];
    if (i < NNODES) {
        int r = ebase + incl - deg;
        g_rowstart[i] = r;
        g_cursor[i] = r;
        g_dinv[i] = rsqrtf(1.0f + (float)deg);
        g_degi[i] = 0;
    }
    if (i == 0) g_rowstart[NNODES] = NEDGES;

    grid_barrier(&g_arr2);

    const int is64 = g_is64;
    const long long* p64 = (const long long*)ei;
    const int* p32 = (const int*)ei;
    for (int e = b * 1024 + t; e < NEDGES; e += NB * 1024) {
        int s, d;
        if (is64) { s = (int)p64[e]; d = (int)p64[NEDGES + e]; }
        else      { s = p32[e];      d = p32[NEDGES + e]; }
        int pos = atomicAdd(&g_cursor[d], 1);
        g_cadj[pos] = make_int2(s, __float_as_int(g_dinv[s]));
    }
}

// ---------------- Layer 1: fp16 gather (direct cadj loads) + MMA GEMM2 epilogue ----------------
#define AGH_STRIDE 272   // bytes per s_aggh row: 128 halfs + 8 pad
#define W2H_STRIDE 80    // bytes per s_w2h row: 32 halfs + 8 pad
__global__ __launch_bounds__(256, 5) void k_layer1(const float* __restrict__ b1,
                                                   const float* __restrict__ W2) {
    __shared__ __align__(16) unsigned char s_aggh[16 * AGH_STRIDE];
    __shared__ __align__(16) unsigned char s_w2h[128 * W2H_STRIDE];

    for (int i = threadIdx.x; i < 128 * 40 / 2; i += blockDim.x)
        ((unsigned int*)s_w2h)[i] = 0u;
    __syncthreads();
    for (int i = threadIdx.x; i < HID * OUTC; i += blockDim.x) {
        int k = i / OUTC, oc = i - k * OUTC;
        *(__half*)(s_w2h + k * W2H_STRIDE + oc * 2) = __float2half_rn(W2[i]);
    }

    const int wid = threadIdx.x >> 5;
    const int lane = threadIdx.x & 31;
    const int h = lane >> 4;
    const int hl = lane & 15;
    const int node = blockIdx.x * 16 + wid * 2 + h;   // exact grid

    {
        float din = g_dinv[node];
        int rs = g_rowstart[node];
        int re = g_rowstart[node + 1];

        uint4 us = *(const uint4*)(g_h1h + (size_t)node * HID + hl * 8);
        const __half2* up = (const __half2*)&us;
        float2 f0 = __half22float2(up[0]), f1 = __half22float2(up[1]);
        float2 f2 = __half22float2(up[2]), f3 = __half22float2(up[3]);
        float di2 = din * din;
        float4 ba = *(const float4*)(b1 + hl * 8);
        float4 bb = *(const float4*)(b1 + hl * 8 + 4);
        float4 acc0, acc1;
        acc0.x = ba.x + di2 * f0.x; acc0.y = ba.y + di2 * f0.y;
        acc0.z = ba.z + di2 * f1.x; acc0.w = ba.w + di2 * f1.y;
        acc1.x = bb.x + di2 * f2.x; acc1.y = bb.y + di2 * f2.y;
        acc1.z = bb.z + di2 * f3.x; acc1.w = bb.w + di2 * f3.y;

        int j = rs;
        for (; j + 4 <= re; j += 4) {
            uint4 u[4]; float w[4];
#pragma unroll
            for (int q = 0; q < 4; q++) {
                int2 e = g_cadj[j + q];          // broadcast load (all lanes)
                w[q] = __int_as_float(e.y) * din;
                u[q] = *(const uint4*)(g_h1h + (size_t)e.x * HID + hl * 8);
            }
#pragma unroll
            for (int q = 0; q < 4; q++) {
                const __half2* vp = (const __half2*)&u[q];
                float2 a = __half22float2(vp[0]), b = __half22float2(vp[1]);
                float2 c = __half22float2(vp[2]), d = __half22float2(vp[3]);
                acc0.x = fmaf(w[q], a.x, acc0.x); acc0.y = fmaf(w[q], a.y, acc0.y);
                acc0.z = fmaf(w[q], b.x, acc0.z); acc0.w = fmaf(w[q], b.y, acc0.w);
                acc1.x = fmaf(w[q], c.x, acc1.x); acc1.y = fmaf(w[q], c.y, acc1.y);
                acc1.z = fmaf(w[q], d.x, acc1.z); acc1.w = fmaf(w[q], d.y, acc1.w);
            }
        }
        for (; j < re; j++) {
            int2 e = g_cadj[j];
            float w = __int_as_float(e.y) * din;
            uint4 u = *(const uint4*)(g_h1h + (size_t)e.x * HID + hl * 8);
            const __half2* vp = (const __half2*)&u;
            float2 a = __half22float2(vp[0]), b = __half22float2(vp[1]);
            float2 c = __half22float2(vp[2]), d = __half22float2(vp[3]);
            acc0.x = fmaf(w, a.x, acc0.x); acc0.y = fmaf(w, a.y, acc0.y);
            acc0.z = fmaf(w, b.x, acc0.z); acc0.w = fmaf(w, b.y, acc0.w);
            acc1.x = fmaf(w, c.x, acc1.x); acc1.y = fmaf(w, c.y, acc1.y);
            acc1.z = fmaf(w, d.x, acc1.z); acc1.w = fmaf(w, d.y, acc1.w);
        }

        __half2 p0 = __floats2half2_rn(fmaxf(acc0.x, 0.f), fmaxf(acc0.y, 0.f));
        __half2 p1 = __floats2half2_rn(fmaxf(acc0.z, 0.f), fmaxf(acc0.w, 0.f));
        __half2 p2 = __floats2half2_rn(fmaxf(acc1.x, 0.f), fmaxf(acc1.y, 0.f));
        __half2 p3 = __floats2half2_rn(fmaxf(acc1.z, 0.f), fmaxf(acc1.w, 0.f));
        uint4 pk;
        pk.x = *(unsigned int*)&p0; pk.y = *(unsigned int*)&p1;
        pk.z = *(unsigned int*)&p2; pk.w = *(unsigned int*)&p3;
        *(uint4*)(s_aggh + (wid * 2 + h) * AGH_STRIDE + hl * 16) = pk;
    }
    __syncthreads();

    // MMA epilogue (warp 0): D[16x18] = s_aggh[16x128] @ s_w2h[128x18]
    if (wid == 0) {
        float acc[3][4];
#pragma unroll
        for (int nt = 0; nt < 3; nt++)
#pragma unroll
            for (int q = 0; q < 4; q++) acc[nt][q] = 0.0f;

#pragma unroll
        for (int kk = 0; kk < 8; kk++) {
            unsigned int a0, a1, a2, a3;
            {
                const unsigned char* p = s_aggh + (lane & 15) * AGH_STRIDE
                                               + kk * 32 + (lane >> 4) * 16;
                unsigned int sa = (unsigned int)__cvta_generic_to_shared(p);
                asm volatile("ldmatrix.sync.aligned.m8n8.x4.shared.b16 {%0,%1,%2,%3}, [%4];"
                             : "=r"(a0), "=r"(a1), "=r"(a2), "=r"(a3) : "r"(sa));
            }
            unsigned int b0, b1, b2, b3, c0, c1, c2, c3;
            {
                const unsigned char* p = s_w2h + (kk * 16 + (lane & 15)) * W2H_STRIDE
                                               + (lane >> 4) * 16;
                unsigned int sb = (unsigned int)__cvta_generic_to_shared(p);
                asm volatile("ldmatrix.sync.aligned.m8n8.x4.trans.shared.b16 {%0,%1,%2,%3}, [%4];"
                             : "=r"(b0), "=r"(b1), "=r"(b2), "=r"(b3) : "r"(sb));
                asm volatile("ldmatrix.sync.aligned.m8n8.x4.trans.shared.b16 {%0,%1,%2,%3}, [%4];"
                             : "=r"(c0), "=r"(c1), "=r"(c2), "=r"(c3) : "r"(sb + 32));
            }
            asm volatile("mma.sync.aligned.m16n8k16.row.col.f32.f16.f16.f32 "
                         "{%0,%1,%2,%3}, {%4,%5,%6,%7}, {%8,%9}, {%0,%1,%2,%3};"
                         : "+f"(acc[0][0]), "+f"(acc[0][1]), "+f"(acc[0][2]), "+f"(acc[0][3])
                         : "r"(a0), "r"(a1), "r"(a2), "r"(a3), "r"(b0), "r"(b1));
            asm volatile("mma.sync.aligned.m16n8k16.row.col.f32.f16.f16.f32 "
                         "{%0,%1,%2,%3}, {%4,%5,%6,%7}, {%8,%9}, {%0,%1,%2,%3};"
                         : "+f"(acc[1][0]), "+f"(acc[1][1]), "+f"(acc[1][2]), "+f"(acc[1][3])
                         : "r"(a0), "r"(a1), "r"(a2), "r"(a3), "r"(b2), "r"(b3));
            asm volatile("mma.sync.aligned.m16n8k16.row.col.f32.f16.f16.f32 "
                         "{%0,%1,%2,%3}, {%4,%5,%6,%7}, {%8,%9}, {%0,%1,%2,%3};"
                         : "+f"(acc[2][0]), "+f"(acc[2][1]), "+f"(acc[2][2]), "+f"(acc[2][3])
                         : "r"(a0), "r"(a1), "r"(a2), "r"(a3), "r"(c0), "r"(c1));
        }

        int gr = lane >> 2;
        int gc = (lane & 3) * 2;
        int n0 = blockIdx.x * 16 + gr;
        int n1 = n0 + 8;
#pragma unroll
        for (int nt = 0; nt < 2; nt++) {
            int c = nt * 8 + gc;
            __half2 hA = __floats2half2_rn(acc[nt][0], acc[nt][1]);
            __half2 hB = __floats2half2_rn(acc[nt][2], acc[nt][3]);
            *(__half2*)(g_h2h + (size_t)n0 * OUTC + c) = hA;
            *(__half2*)(g_h2h + (size_t)n1 * OUTC + c) = hB;
        }
        if (gc == 0) {
            __half2 hA = __floats2half2_rn(acc[2][0], acc[2][1]);
            __half2 hB = __floats2half2_rn(acc[2][2], acc[2][3]);
            *(__half2*)(g_h2h + (size_t)n0 * OUTC + 16) = hA;
            *(__half2*)(g_h2h + (size_t)n1 * OUTC + 16) = hB;
        }
    }
}

// ---------------- Layer 2: 2 nodes/warp, direct cadj loads, log_softmax ----------------
__global__ __launch_bounds__(256) void k_layer2(const float* __restrict__ b2,
                                                float* __restrict__ out) {
    const int wid = threadIdx.x >> 5;
    const int lane = threadIdx.x & 31;
    const int h = lane >> 4;
    const int hl = lane & 15;
    const unsigned hmask = h ? 0xffff0000u : 0x0000ffffu;
    const int node = blockIdx.x * 16 + wid * 2 + h;
    if (node >= NNODES) return;

    float din = g_dinv[node];
    int rs = g_rowstart[node];
    int re = g_rowstart[node + 1];

    float2 acc = make_float2(0.f, 0.f);
    if (hl < 9) {
        __half2 hv = *(const __half2*)(g_h2h + (size_t)node * OUTC + 2 * hl);
        float2 f = __half22float2(hv);
        float di2 = din * din;
        acc.x = b2[2 * hl]     + di2 * f.x;
        acc.y = b2[2 * hl + 1] + di2 * f.y;
    }

    int j = rs;
    for (; j + 4 <= re; j += 4) {
        float2 v[4]; float w[4];
#pragma unroll
        for (int q = 0; q < 4; q++) {
            int2 e = g_cadj[j + q];              // broadcast load
            w[q] = __int_as_float(e.y) * din;
            v[q] = make_float2(0.f, 0.f);
            if (hl < 9)
                v[q] = __half22float2(*(const __half2*)(g_h2h + (size_t)e.x * OUTC + 2 * hl));
        }
#pragma unroll
        for (int q = 0; q < 4; q++) {
            acc.x = fmaf(w[q], v[q].x, acc.x);
            acc.y = fmaf(w[q], v[q].y, acc.y);
        }
    }
    for (; j < re; j++) {
        int2 e = g_cadj[j];
        float w = __int_as_float(e.y) * din;
        if (hl < 9) {
            float2 v = __half22float2(*(const __half2*)(g_h2h + (size_t)e.x * OUTC + 2 * hl));
            acc.x = fmaf(w, v.x, acc.x);
            acc.y = fmaf(w, v.y, acc.y);
        }
    }

    float m = (hl < 9) ? fmaxf(acc.x, acc.y) : -1e30f;
#pragma unroll
    for (int off = 8; off; off >>= 1)
        m = fmaxf(m, __shfl_xor_sync(hmask, m, off));
    float e = (hl < 9) ? (expf(acc.x - m) + expf(acc.y - m)) : 0.f;
#pragma unroll
    for (int off = 8; off; off >>= 1)
        e += __shfl_xor_sync(hmask, e, off);
    float ls = m + logf(e);
    if (hl < 9) {
        float2 o = make_float2(acc.x - ls, acc.y - ls);
        *(float2*)(out + (size_t)node * OUTC + 2 * hl) = o;
    }
}

// ---------------- launch ----------------
extern "C" void kernel_launch(void* const* d_in, const int* in_sizes, int n_in,
                              void* d_out, int out_size) {
    const float* x = 0; const void* ei = 0;
    const float* W1 = 0; const float* b1 = 0;
    const float* W2 = 0; const float* b2 = 0;
    for (int i = 0; i < n_in; i++) {
        long long sz = in_sizes[i];
        if (sz == (long long)NNODES * INC) x = (const float*)d_in[i];
        else if (sz == 2LL * NEDGES)       ei = d_in[i];
        else if (sz == (long long)INC * HID) W1 = (const float*)d_in[i];
        else if (sz == HID)                b1 = (const float*)d_in[i];
        else if (sz == (long long)HID * OUTC) W2 = (const float*)d_in[i];
        else if (sz == OUTC)               b2 = (const float*)d_in[i];
    }
    float* out = (float*)d_out;

    cudaFuncSetAttribute(k_gemm1_mma, cudaFuncAttributeMaxDynamicSharedMemorySize, GEMM1_SMEM);

    k_prep<<<(NNODES * INC / 4 + 255) / 256, 256>>>(ei, x, W1);                      // 1
    k_gemm1_mma<<<(NNODES + 127) / 128, 512, GEMM1_SMEM>>>();                        // 2
    k_scanfill<<<NB, 1024>>>(ei);                                                    // 3
    k_layer1<<<NNODES / 16, 256>>>(b1, W2);                                          // 4 (profiled)
    {
        long long thr = (long long)NNODES * 16;
        k_layer2<<<(unsigned)((thr + 255) / 256), 256>>>(b2, out);                   // 5
    }
}